// round 17
// baseline (speedup 1.0000x reference)
#include <cuda_runtime.h>
#include <cuda_bf16.h>
#include <cstdint>

#define B_      32
#define TENC    512
#define TDEC    32
#define DIM     256
#define VOCAB_  32000
#define SOS_    1
#define NROW    (TDEC * B_)                 // 1024 rows, row = t*32 + b
#define NTILE_E 1024                        // enc GEMM tiles
#define NTILE_H 96                          // hV/uch GEMM tiles
#define NU_EN   512                         // energy units: (tc,b,tq)
#define NQ_BETA 128                         // beta units: (tc? no: b, tchunk8) -> 32*4
#define NQ_ATTN 32                          // attn tiles 16m x 2n
#define NQ_VOC  4000                        // vocab tiles 16m x 250n
#define NQ_ALL  (NQ_BETA + NQ_ATTN + NQ_VOC)

// ---------------- device scratch ----------------
__device__ float g_encW[B_ * TENC * 512];
__device__ float g_H[NROW * DIM];
__device__ float g_hVm2[NROW * DIM];
__device__ float g_hVc2[NROW * DIM];
__device__ float g_uch2[NROW * DIM];
__device__ float g_p2[NROW * TENC];
__device__ float g_ecb2[NROW * TENC];
__device__ float g_alpha2[NROW * TENC];
__device__ float g_ctx2[NROW * DIM];
__device__ float g_attn[NROW * DIM];
__device__ float g_xw[B_ * (TDEC + 1) * DIM];
__device__ float g_WihT[256 * 256];
__device__ float g_WhhT[256 * 256];
__device__ float g_Wmc[512 * 256];          // rows: o<256 Wm, else Wc
__device__ float g_Wch[256 * 256];          // Wcomb h-half raw rows
__device__ float g_Wcc[256 * 256];          // Wcomb ctx-half raw rows
__device__ float g_bmc[512];
__device__ float g_biasr[256];
__device__ float g_wm[256];
__device__ float g_wc[256];
__device__ float g_cst[2];
__device__ float g_zero[256];
__device__ unsigned g_hcnt[TDEC];           // batches finished H_t
__device__ unsigned g_ucnt[NROW];           // energy quarters done per (b,t) row (max 4)
__device__ unsigned g_bcnt[4];              // beta units done per t-chunk (max 32)
__device__ unsigned g_acnt[16];             // attn tiles done per m (max 2)
__device__ unsigned g_q;                    // tail queue

// ---------------- shared memory ----------------
struct SmSt {
    float alpha[512];
    float h[256];
    float eu[512], ratio[512], beta[512];
    float ctx[256];
    float part[1024];
    float w8[32];
};
struct SmEn {                               // energy unit: 8 hV vectors
    float hm[8][256];
    float hc[8][256];
};
struct SmK4 {                               // tail beta unit
    float beta8[8][512];                    // 16 KB
    float part[4][4][256];                  // 16 KB (4 tt-quarters x 4 t x 256)
    float eu[512], ratio[512];
    float w8[32];
};
struct __align__(16) SmGm {
    unsigned long long Ap[64][10];
    unsigned long long Bp[128][10];
};
union SmU {
    SmSt st;
    SmEn en;
    SmK4 k4;
    SmGm gm;
};

// ---------------- helpers ----------------
__device__ __forceinline__ float warp_sum(float v) {
#pragma unroll
    for (int s = 16; s; s >>= 1) v += __shfl_xor_sync(0xffffffffu, v, s);
    return v;
}
__device__ __forceinline__ float tanh_fast(float x) {
    float e = __expf(2.0f * x);
    return 1.0f - __fdividef(2.0f, e + 1.0f);
}
__device__ __forceinline__ float tanh_hw(float x) {
    float y;
    asm("tanh.approx.f32 %0, %1;" : "=f"(y) : "f"(x));
    return y;
}
__device__ __forceinline__ float sigmoid_fast(float x) {
    return __fdividef(1.0f, 1.0f + __expf(-x));
}
__device__ __forceinline__ unsigned long long pk2(float lo, float hi) {
    unsigned long long r;
    asm("mov.b64 %0, {%1, %2};" : "=l"(r) : "f"(lo), "f"(hi));
    return r;
}
__device__ __forceinline__ void fma2(unsigned long long& acc, unsigned long long a,
                                     unsigned long long b) {
    asm("fma.rn.f32x2 %0, %1, %2, %0;" : "+l"(acc) : "l"(a), "l"(b));
}
__device__ __forceinline__ void unpack2(unsigned long long v, float& lo, float& hi) {
    asm("mov.b64 {%0, %1}, %2;" : "=f"(lo), "=f"(hi) : "l"(v));
}

__device__ __forceinline__ float pair_excl(float ps, float* s_w8) {
    int tid = threadIdx.x, lane = tid & 31, wid = tid >> 5;
    float s = ps;
#pragma unroll
    for (int d = 1; d < 32; d <<= 1) {
        float n = __shfl_up_sync(0xffffffffu, s, d);
        if (lane >= d) s += n;
    }
    __syncthreads();
    if (lane == 31) s_w8[wid] = s;
    __syncthreads();
    if (tid < 32) {
        float v = (lane < 8) ? s_w8[lane] : 0.0f;
#pragma unroll
        for (int d = 1; d < 8; d <<= 1) {
            float n = __shfl_up_sync(0xffffffffu, v, d);
            if (lane >= d) v += n;
        }
        if (lane < 8) s_w8[lane] = v;
    }
    __syncthreads();
    float woff = wid ? s_w8[wid - 1] : 0.0f;
    return woff + (s - ps);
}

__device__ __forceinline__ float max512(float m, float* s_w8) {
    int tid = threadIdx.x, lane = tid & 31, wid = tid >> 5;
#pragma unroll
    for (int s = 16; s; s >>= 1) m = fmaxf(m, __shfl_xor_sync(0xffffffffu, m, s));
    __syncthreads();
    if (lane == 0) s_w8[wid] = m;
    __syncthreads();
    if (tid < 32) {
        float v = (lane < 8) ? s_w8[lane] : -1e30f;
#pragma unroll
        for (int s = 4; s; s >>= 1) v = fmaxf(v, __shfl_xor_sync(0xffffffffu, v, s));
        if (lane == 0) s_w8[0] = v;
    }
    __syncthreads();
    return s_w8[0];
}

__device__ __forceinline__ float gemv256(const float* __restrict__ WT,
                                         const float* __restrict__ x, float* s_part) {
    int tid = threadIdx.x;
    int j = tid & 63, kq = tid >> 6;
    __syncthreads();
    const float4* Wp = reinterpret_cast<const float4*>(WT);
    float4 acc = make_float4(0.f, 0.f, 0.f, 0.f);
    int k0 = kq * 64;
#pragma unroll 8
    for (int k = k0; k < k0 + 64; ++k) {
        float f = x[k];
        float4 w = Wp[(size_t)k * 64 + j];
        acc.x = fmaf(f, w.x, acc.x);
        acc.y = fmaf(f, w.y, acc.y);
        acc.z = fmaf(f, w.z, acc.z);
        acc.w = fmaf(f, w.w, acc.w);
    }
    reinterpret_cast<float4*>(s_part)[kq * 64 + j] = acc;
    __syncthreads();
    return s_part[tid] + s_part[256 + tid] + s_part[512 + tid] + s_part[768 + tid];
}

__device__ __forceinline__ void spin_cta(const unsigned* flag, unsigned v) {
    if (threadIdx.x == 0) {
        const volatile unsigned* f = (const volatile unsigned*)flag;
        while (*f < v) {}
    }
    __syncthreads();
    __threadfence();
}
__device__ __forceinline__ void spin_cta_multi(unsigned* base, int i0, int n, unsigned v) {
    if (threadIdx.x < (unsigned)n) {
        const volatile unsigned* f = (const volatile unsigned*)(base + i0 + threadIdx.x);
        while (*f < v) {}
    }
    __syncthreads();
    __threadfence();
}

// ---------------- GEMM tile: C[64,128] = A[64x256] @ B[128x256]^T, K=256 --------
// EPI: 0 = +bias store; 1 = tanh(acc + g_uch2[row,col]) store (bias ignored)
template <bool REMAP, bool ACG, int EPI>
__device__ void gemm_tile64(const float* __restrict__ A, const float* __restrict__ Bw,
                            const float* __restrict__ bias, float* __restrict__ C, int bm,
                            int bn, int N, SmGm* sg) {
    const int K = 256;
    int tid = threadIdx.x, tx = tid & 15, ty = tid >> 4;
    int lrowA = tid >> 2, kbA = (tid & 3) * 2;
    int lrowB = tid >> 1, kbB = (tid & 1) * 4;
    const float* Aptr = A + (size_t)(bm + lrowA) * K + (tid & 3) * 4;
    const float* Bptr = Bw + (size_t)(bn + lrowB) * K + (tid & 1) * 8;

    unsigned long long acc[4][8];
#pragma unroll
    for (int r = 0; r < 4; ++r)
#pragma unroll
        for (int c = 0; c < 8; ++c) acc[r][c] = 0ull;

    float4 fa, fb0, fb1;
    fa = ACG ? __ldcg((const float4*)Aptr) : *(const float4*)Aptr;
    fb0 = *(const float4*)Bptr;
    fb1 = *(const float4*)(Bptr + 4);

#pragma unroll 1
    for (int k0 = 0; k0 < K; k0 += 16) {
        sg->Ap[lrowA][kbA + 0] = pk2(fa.x, fa.y);
        sg->Ap[lrowA][kbA + 1] = pk2(fa.z, fa.w);
        sg->Bp[lrowB][kbB + 0] = pk2(fb0.x, fb0.y);
        sg->Bp[lrowB][kbB + 1] = pk2(fb0.z, fb0.w);
        sg->Bp[lrowB][kbB + 2] = pk2(fb1.x, fb1.y);
        sg->Bp[lrowB][kbB + 3] = pk2(fb1.z, fb1.w);
        __syncthreads();
        if (k0 + 16 < K) {
            fa = ACG ? __ldcg((const float4*)(Aptr + k0 + 16))
                     : *(const float4*)(Aptr + k0 + 16);
            fb0 = *(const float4*)(Bptr + k0 + 16);
            fb1 = *(const float4*)(Bptr + k0 + 20);
        }
#pragma unroll
        for (int u = 0; u < 4; ++u) {
            ulonglong2 a2[4], b2[8];
#pragma unroll
            for (int r = 0; r < 4; ++r)
                a2[r] = *reinterpret_cast<const ulonglong2*>(&sg->Ap[ty + 16 * r][2 * u]);
#pragma unroll
            for (int c = 0; c < 8; ++c)
                b2[c] = *reinterpret_cast<const ulonglong2*>(&sg->Bp[tx + 16 * c][2 * u]);
#pragma unroll
            for (int r = 0; r < 4; ++r)
#pragma unroll
                for (int c = 0; c < 8; ++c) {
                    fma2(acc[r][c], a2[r].x, b2[c].x);
                    fma2(acc[r][c], a2[r].y, b2[c].y);
                }
        }
        __syncthreads();
    }

    float bb[8];
    if (EPI == 0) {
#pragma unroll
        for (int c = 0; c < 8; ++c) bb[c] = __ldg(&bias[bn + tx + 16 * c]);
    }
#pragma unroll
    for (int r = 0; r < 4; ++r) {
        int row = bm + ty + 16 * r;
        float* crow;
        if (REMAP) {
            crow = C + (size_t)((row & 31) * TDEC + (row >> 5)) * N;
        } else {
            crow = C + (size_t)row * N;
        }
#pragma unroll
        for (int c = 0; c < 8; ++c) {
            float lo, hi;
            unpack2(acc[r][c], lo, hi);
            float v = lo + hi;
            int col = bn + tx + 16 * c;
            if (EPI == 0) {
                crow[col] = v + bb[c];
            } else {
                crow[col] = tanh_fast(v + __ldcg(&g_uch2[(size_t)row * DIM + col]));
            }
        }
    }
}

// ---------------- init ----------------
__global__ void k_init(const float* __restrict__ W_ih, const float* __restrict__ b_ih,
                       const float* __restrict__ W_hh, const float* __restrict__ b_hh,
                       const float* __restrict__ W_comb, const float* __restrict__ Wm,
                       const float* __restrict__ Wc, const float* __restrict__ bm,
                       const float* __restrict__ bc, const float* __restrict__ vvm,
                       const float* __restrict__ gm, const float* __restrict__ vbm,
                       const float* __restrict__ rm, const float* __restrict__ vvc,
                       const float* __restrict__ gc, const float* __restrict__ vbc,
                       const float* __restrict__ rc) {
    int bidx = blockIdx.x, tid = threadIdx.x;
    if (bidx < 96) {
        for (int idx = bidx * 256 + tid; idx < 458752; idx += 96 * 256) {
            if (idx < 65536) {
                int k = idx >> 8, o = idx & 255;
                g_WihT[idx] = W_ih[o * 256 + k];
            } else if (idx < 131072) {
                int r = idx - 65536;
                int k = r >> 8, o = r & 255;
                g_WhhT[r] = W_hh[o * 256 + k];
            } else if (idx < 262144) {
                int r = idx - 131072;
                int o = r >> 8, k = r & 255;
                g_Wmc[r] = (o < 256) ? Wm[o * 256 + k] : Wc[(o - 256) * 256 + k];
            } else if (idx < 327680) {
                int r = idx - 262144;
                int o = r >> 8, k = r & 255;
                g_Wch[r] = W_comb[o * 512 + 256 + k];
            } else if (idx < 393216) {
                int r = idx - 327680;
                int o = r >> 8, k = r & 255;
                g_Wcc[r] = W_comb[o * 512 + k];
            } else {
                int r = idx - 393216;    // zero ucnt (1024 words) + others
                if (r < NROW) g_ucnt[r] = 0u;
            }
        }
    } else {
        __shared__ float red[256];
        if (tid < TDEC) g_hcnt[tid] = 0u;
        if (tid < 16) g_acnt[tid] = 0u;
        if (tid < 4) g_bcnt[tid] = 0u;
        if (tid == 0) g_q = 0u;
        g_zero[tid] = 0.0f;
        g_bmc[tid] = bm[tid];
        g_bmc[256 + tid] = bc[tid];
        float v = vvm[tid];
        red[tid] = v * v;
        __syncthreads();
        for (int s = 128; s > 0; s >>= 1) {
            if (tid < s) red[tid] += red[tid + s];
            __syncthreads();
        }
        float nm = sqrtf(red[0]);
        __syncthreads();
        g_wm[tid] = vvm[tid] * gm[0] / nm;
        float v2 = vvc[tid];
        red[tid] = v2 * v2;
        __syncthreads();
        for (int s = 128; s > 0; s >>= 1) {
            if (tid < s) red[tid] += red[tid + s];
            __syncthreads();
        }
        float nc = sqrtf(red[0]);
        __syncthreads();
        g_wc[tid] = vvc[tid] * gc[0] / nc;
        g_biasr[tid] = b_ih[tid] + b_hh[tid];
        if (tid == 0) {
            g_cst[0] = vbm[0] + rm[0];
            g_cst[1] = vbc[0] + rc[0];
        }
    }
}

// ---------------- token projections ----------------
__global__ __launch_bounds__(256) void k_xw(const int* __restrict__ dec,
                                            const float* __restrict__ emb) {
    __shared__ float s_x[256];
    __shared__ float s_part[1024];
    int t = blockIdx.x, b = blockIdx.y, tid = threadIdx.x;
    int tok = (t == 0) ? SOS_ : dec[b * TDEC + (t - 1)];
    s_x[tid] = __ldg(&emb[(size_t)tok * DIM + tid]);
    float y = gemv256(g_WihT, s_x, s_part) + g_biasr[tid];
    g_xw[((size_t)b * (TDEC + 1) + t) * DIM + tid] = y;
}

// ---------------- k1: H chains (32 CTAs) + enc/hV/uch GEMMs (workers) ----------------
__global__ __launch_bounds__(256, 2) void k_phase1(const float* __restrict__ enc,
                                                   const float* __restrict__ h0,
                                                   const float* __restrict__ Vm,
                                                   const float* __restrict__ Vc) {
    __shared__ SmU su;
    int tid = threadIdx.x, cta = blockIdx.x;
    int nw = gridDim.x - 32;

    if (cta < 32) {
        int b = cta;
        su.st.h[tid] = h0[b * DIM + tid];
#pragma unroll 1
        for (int t = 0; t < TDEC; ++t) {
            float yh = gemv256(g_WhhT, su.st.h, su.st.part);
            float hn =
                tanh_fast(yh + __ldg(&g_xw[((size_t)b * (TDEC + 1) + t) * DIM + tid]));
            __syncthreads();
            su.st.h[tid] = hn;
            __stcg(&g_H[((size_t)t * B_ + b) * DIM + tid], hn);
            __threadfence();
            __syncthreads();
            if (tid == 0) atomicAdd(&g_hcnt[t], 1u);
        }
    } else {
        int w = cta - 32;
        for (int idx = w; idx < NTILE_E; idx += nw) {
            gemm_tile64<false, false, 0>(enc, g_Wmc, g_bmc, g_encW, (idx >> 2) * 64,
                                         (idx & 3) * 128, 512, &su.gm);
        }
        for (int idx = w; idx < NTILE_H; idx += nw) {
            int g2 = idx / 32, r = idx - g2 * 32;
            int m = r >> 1, n = r & 1;
            spin_cta_multi(g_hcnt, 2 * m, 2, 32u);
            const float* Bw = (g2 == 0) ? Vm : (g2 == 1) ? Vc : g_Wch;
            float* C = (g2 == 0) ? g_hVm2 : (g2 == 1) ? g_hVc2 : g_uch2;
            gemm_tile64<false, true, 0>(g_H, Bw, g_zero, C, m * 64, n * 128, 256, &su.gm);
        }
    }
}

// ---------------- k2: energy (t-tiled) + alpha chains ----------------
// grid 444: CTA 0-31 = alpha chain per batch; 32..443 = energy workers.
// Energy unit u (0..511): tc=u>>7 (t-chunk of 8), b=(u>>2)&31, tq=u&3 (tt quarter).
__global__ __launch_bounds__(256, 3) void k_enalpha(const float* __restrict__ noise) {
    __shared__ SmU su;
    int tid = threadIdx.x, cta = blockIdx.x;

    if (cta < 32) {
        // ---- alpha chain for batch b ----
        int b = cta;
        su.st.alpha[tid] = (tid == 0) ? 1.0f : 0.0f;
        su.st.alpha[256 + tid] = 0.0f;
        __syncthreads();
#pragma unroll 1
        for (int t = 0; t < TDEC; ++t) {
            int row = t * B_ + b;
            spin_cta(&g_ucnt[row], 4u);
            int j0 = 2 * tid, j1 = 2 * tid + 1;
            float p0 = __ldcg(&g_p2[(size_t)row * TENC + j0]);
            float p1 = __ldcg(&g_p2[(size_t)row * TENC + j1]);
            float l0 = __logf(fminf(fmaxf(1.0f - p0, 1e-10f), 1.0f));
            float l1 = __logf(fminf(fmaxf(1.0f - p1, 1e-10f), 1.0f));
            float eP = pair_excl(l0 + l1, su.st.w8);
            float cp0 = __expf(eP);
            float cp1 = __expf(eP + l0);
            float A0 = su.st.alpha[j0], A1 = su.st.alpha[j1];
            float r0 = __fdividef(A0, fmaxf(cp0, 1e-10f));
            float r1 = __fdividef(A1, fmaxf(cp1, 1e-10f));
            float eS = pair_excl(r0 + r1, su.st.w8);
            float na0 = p0 * cp0 * (eS + r0);
            float na1 = p1 * cp1 * (eS + r0 + r1);
            su.st.alpha[j0] = na0;
            su.st.alpha[j1] = na1;
            __stcg(&g_alpha2[(size_t)row * TENC + j0], na0);
            __stcg(&g_alpha2[(size_t)row * TENC + j1], na1);
        }
    } else {
        // ---- energy workers ----
        int lane = tid & 31, wid = tid >> 5;
        int a0 = lane * 8;
        float cm = g_cst[0], cc = g_cst[1];
        float rwm[8], rwc[8];
#pragma unroll
        for (int j = 0; j < 8; ++j) {
            rwm[j] = __ldg(&g_wm[a0 + j]);
            rwc[j] = __ldg(&g_wc[a0 + j]);
        }
        int nw = gridDim.x - 32;
#pragma unroll 1
        for (int u = cta - 32; u < NU_EN; u += nw) {
            int tc = u >> 7, b = (u >> 2) & 31, tq = u & 3;
            // load 8 hV vector pairs into smem
            __syncthreads();
            for (int i = tid; i < 2048; i += 256) {
                int t8 = i >> 8, c = i & 255;
                int row = (tc * 8 + t8) * B_ + b;
                su.en.hm[t8][c] = __ldcg(&g_hVm2[(size_t)row * DIM + c]);
                su.en.hc[t8][c] = __ldcg(&g_hVc2[(size_t)row * DIM + c]);
            }
            __syncthreads();
            const size_t base = (size_t)b * TENC;
#pragma unroll 1
            for (int tt = tq * 128 + wid; tt < tq * 128 + 128; tt += 8) {
                const float4* row4 =
                    reinterpret_cast<const float4*>(g_encW + (base + tt) * 512);
                float4 m0 = __ldcg(row4 + lane * 2), m1 = __ldcg(row4 + lane * 2 + 1);
                float4 c0 = __ldcg(row4 + 64 + lane * 2),
                       c1 = __ldcg(row4 + 64 + lane * 2 + 1);
                float mv[8] = {m0.x, m0.y, m0.z, m0.w, m1.x, m1.y, m1.z, m1.w};
                float cv[8] = {c0.x, c0.y, c0.z, c0.w, c1.x, c1.y, c1.z, c1.w};
#pragma unroll 1
                for (int t8 = 0; t8 < 8; ++t8) {
                    float am = 0.f, ac = 0.f;
#pragma unroll
                    for (int j = 0; j < 8; ++j) {
                        am = fmaf(tanh_hw(mv[j] + su.en.hm[t8][a0 + j]), rwm[j], am);
                        ac = fmaf(tanh_hw(cv[j] + su.en.hc[t8][a0 + j]), rwc[j], ac);
                    }
                    am = warp_sum(am);
                    ac = warp_sum(ac);
                    if (lane == 0) {
                        int t = tc * 8 + t8;
                        int row = t * B_ + b;
                        float pp = sigmoid_fast(
                            am + cm +
                            __ldg(&noise[((size_t)t * B_ + b) * TENC + tt]));
                        __stcg(&g_p2[(size_t)row * TENC + tt], pp);
                        __stcg(&g_ecb2[(size_t)row * TENC + tt], ac + cc);
                    }
                }
            }
            __threadfence();
            __syncthreads();
            if (tid < 8) atomicAdd(&g_ucnt[(tc * 8 + tid) * B_ + b], 1u);
        }
    }
}

// ---------------- k3: tail queue — beta/ctx units -> attn tiles -> vocab tiles -------
__global__ __launch_bounds__(256, 2) void k_tail(const float* __restrict__ enc,
                                                 const float* __restrict__ Wproj,
                                                 const float* __restrict__ bproj,
                                                 float* __restrict__ out) {
    __shared__ SmU su;
    __shared__ int s_idx;
    int tid = threadIdx.x;

    for (;;) {
        __syncthreads();
        if (tid == 0) s_idx = (int)atomicAdd(&g_q, 1u);
        __syncthreads();
        int idx = s_idx;
        if (idx >= NQ_ALL) break;

        if (idx < NQ_BETA) {
            // ---- beta + context unit: (b, t-chunk of 8) ----
            int tc = idx >> 5, b = idx & 31;
            // 1) build 8 beta rows in smem
#pragma unroll 1
            for (int t8 = 0; t8 < 8; ++t8) {
                int row = (tc * 8 + t8) * B_ + b;
                int j0 = 2 * tid, j1 = 2 * tid + 1;
                float e0 = __ldcg(&g_ecb2[(size_t)row * TENC + j0]);
                float e1 = __ldcg(&g_ecb2[(size_t)row * TENC + j1]);
                float mx = max512(fmaxf(e0, e1), su.k4.w8);
                float eu0 = __expf(e0 - mx), eu1 = __expf(e1 - mx);
                su.k4.eu[j0] = eu0;
                su.k4.eu[j1] = eu1;
                __syncthreads();
                float d0 = 0.0f, d1 = 0.0f;
#pragma unroll
                for (int k = 0; k < 8; ++k) {
                    int q0i = j0 - k, q1i = j1 - k;
                    if (q0i >= 0) d0 += su.k4.eu[q0i];
                    if (q1i >= 0) d1 += su.k4.eu[q1i];
                }
                float a0v = __ldcg(&g_alpha2[(size_t)row * TENC + j0]);
                float a1v = __ldcg(&g_alpha2[(size_t)row * TENC + j1]);
                su.k4.ratio[j0] = __fdividef(a0v, fmaxf(d0, 1e-10f));
                su.k4.ratio[j1] = __fdividef(a1v, fmaxf(d1, 1e-10f));
                __syncthreads();
                float b0 = 0.0f, b1 = 0.0f;
#pragma unroll
                for (int k = 0; k < 8; ++k) {
                    int q0i = j0 + k, q1i = j1 + k;
                    if (q0i < TENC) b0 += su.k4.ratio[q0i];
                    if (q1i < TENC) b1 += su.k4.ratio[q1i];
                }
                su.k4.beta8[t8][j0] = eu0 * b0;
                su.k4.beta8[t8][j1] = eu1 * b1;
                __syncthreads();
            }
            // 2) two enc passes accumulate contexts for 4 t's each
#pragma unroll 1
            for (int p = 0; p < 2; ++p) {
                int jq = tid >> 6, e4 = tid & 63;
                float4 acc[4];
#pragma unroll
                for (int k = 0; k < 4; ++k) acc[k] = make_float4(0.f, 0.f, 0.f, 0.f);
                const float4* ep = reinterpret_cast<const float4*>(enc) +
                                   (size_t)(b * TENC + jq * 128) * (DIM / 4) + e4;
#pragma unroll 2
                for (int tt = 0; tt < 128; ++tt) {
                    float4 ev = ep[(size_t)tt * 64];
#pragma unroll
                    for (int k = 0; k < 4; ++k) {
                        float f = su.k4.beta8[p * 4 + k][jq * 128 + tt];
                        acc[k].x = fmaf(f, ev.x, acc[k].x);
                        acc[k].y = fmaf(f, ev.y, acc[k].y);
                        acc[k].z = fmaf(f, ev.z, acc[k].z);
                        acc[k].w = fmaf(f, ev.w, acc[k].w);
                    }
                }
#pragma unroll
                for (int k = 0; k < 4; ++k)
                    reinterpret_cast<float4*>(su.k4.part[jq][k])[e4] = acc[k];
                __syncthreads();
#pragma unroll
                for (int k = 0; k < 4; ++k) {
                    int row = (tc * 8 + p * 4 + k) * B_ + b;
                    float v = su.k4.part[0][k][tid] + su.k4.part[1][k][tid] +
                              su.k4.part[2][k][tid] + su.k4.part[3][k][tid];
                    __stcg(&g_ctx2[(size_t)row * DIM + tid], v);
                }
                __syncthreads();
            }
            __threadfence();
            __syncthreads();
            if (tid == 0) atomicAdd(&g_bcnt[tc], 1u);
        } else if (idx < NQ_BETA + NQ_ATTN) {
            // ---- attn tile: tanh(ctx @ Wcc^T + uch) ----
            int a = idx - NQ_BETA;
            int m = a >> 1, n = a & 1;
            spin_cta(&g_bcnt[m >> 2], 32u);
            gemm_tile64<false, true, 1>(g_ctx2, g_Wcc, g_zero, g_attn, m * 64, n * 128,
                                        256, &su.gm);
            __threadfence();
            __syncthreads();
            if (tid == 0) atomicAdd(&g_acnt[m], 1u);
        } else {
            // ---- vocab tile ----
            int v = idx - NQ_BETA - NQ_ATTN;
            int m = v / (VOCAB_ / 128);
            int n = v - m * (VOCAB_ / 128);
            spin_cta(&g_acnt[m], 2u);
            gemm_tile64<true, true, 0>(g_attn, Wproj, bproj, out, m * 64, n * 128, VOCAB_,
                                       &su.gm);
        }
    }
}

// ---------------- launch ----------------
extern "C" void kernel_launch(void* const* d_in, const int* in_sizes, int n_in, void* d_out,
                              int out_size) {
    (void)in_sizes;
    (void)n_in;
    (void)out_size;
    const float* enc = (const float*)d_in[0];
    const int* dec = (const int*)d_in[1];
    const float* h0 = (const float*)d_in[2];
    const float* noise = (const float*)d_in[3];
    const float* emb = (const float*)d_in[4];
    const float* W_ih = (const float*)d_in[5];
    const float* b_ih = (const float*)d_in[6];
    const float* W_hh = (const float*)d_in[7];
    const float* b_hh = (const float*)d_in[8];
    const float* Wm = (const float*)d_in[9];
    const float* Vm = (const float*)d_in[10];
    const float* bm = (const float*)d_in[11];
    const float* vvm = (const float*)d_in[12];
    const float* gm = (const float*)d_in[13];
    const float* vbm = (const float*)d_in[14];
    const float* rm = (const float*)d_in[15];
    const float* Wc = (const float*)d_in[16];
    const float* Vc = (const float*)d_in[17];
    const float* bc = (const float*)d_in[18];
    const float* vvc = (const float*)d_in[19];
    const float* gc = (const float*)d_in[20];
    const float* vbc = (const float*)d_in[21];
    const float* rc = (const float*)d_in[22];
    const float* W_comb = (const float*)d_in[23];
    const float* W_proj = (const float*)d_in[24];
    const float* b_proj = (const float*)d_in[25];
    float* out = (float*)d_out;

    k_init<<<97, 256>>>(W_ih, b_ih, W_hh, b_hh, W_comb, Wm, Wc, bm, bc, vvm, gm, vbm, rm,
                        vvc, gc, vbc, rc);
    k_xw<<<dim3(TDEC + 1, B_), 256>>>(dec, emb);
    k_phase1<<<296, 256>>>(enc, h0, Vm, Vc);
    k_enalpha<<<444, 256>>>(noise);
    k_tail<<<296, 256>>>(enc, W_proj, b_proj, out);
}